// round 14
// baseline (speedup 1.0000x reference)
#include <cuda_runtime.h>
#include <cuda_bf16.h>
#include <math.h>
#include <stdint.h>

#define CDIM 256
#define NDIM 4096
#define BDIM 8
#define QR   64
#define TK   32
#define NT   (NDIM / TK)   // 128

__device__ __nv_bfloat16 g_q[(size_t)BDIM * NDIM * CDIM];   // [b][n][c]
__device__ __nv_bfloat16 g_k[(size_t)BDIM * NDIM * CDIM];   // [b][n][c]
__device__ __nv_bfloat16 g_v[(size_t)BDIM * NDIM * CDIM];   // [b][c][n] (transposed)
__device__ __nv_bfloat16 g_xh[(size_t)BDIM * NDIM * CDIM];  // x^T hi [b][n][c]
__device__ __nv_bfloat16 g_xl[(size_t)BDIM * NDIM * CDIM];  // x^T lo
__device__ __nv_bfloat16 g_wh[4 * CDIM * CDIM];             // W hi [p][o][c]
__device__ __nv_bfloat16 g_wl[4 * CDIM * CDIM];             // W lo

// ---- attn smem byte offsets (QR=64, TK=32; 96KB -> 2 CTAs/SM) ----
#define SQ_OFF 0u          // 64 x 256 bf16 (row 512B) = 32KB
#define SK_OFF 32768u      // 2 x (32 x 256 bf16) = 32KB
#define SV_OFF 65536u      // 2 x (256 x 32 bf16, row 64B) = 32KB
#define SM_BYTES 98304u

// ---- proj2 smem byte offsets (per buffer; 2 buffers) ----
#define P2_XH 0u
#define P2_XL 16384u
#define P2_WH 32768u
#define P2_WL 65536u
#define P2_BUF 98304u
#define P2_BYTES 196608u

// ---------------- helpers ----------------
__device__ __forceinline__ uint32_t smem_u32(const void* p) {
    uint32_t a;
    asm("{ .reg .u64 t; cvta.to.shared.u64 t, %1; cvt.u32.u64 %0, t; }" : "=r"(a) : "l"(p));
    return a;
}
__device__ __forceinline__ float ex2(float x) {
    float y; asm("ex2.approx.f32 %0, %1;" : "=f"(y) : "f"(x)); return y;
}
__device__ __forceinline__ uint32_t bf2(float lo, float hi) {
    __nv_bfloat162 h = __float22bfloat162_rn(make_float2(lo, hi));
    return *(uint32_t*)&h;
}
__device__ __forceinline__ void cp16(uint32_t saddr, const void* gaddr) {
    asm volatile("cp.async.cg.shared.global [%0], [%1], 16;" :: "r"(saddr), "l"(gaddr));
}
__device__ __forceinline__ void cp_commit() {
    asm volatile("cp.async.commit_group;" ::: "memory");
}
template <int N>
__device__ __forceinline__ void cp_wait() {
    asm volatile("cp.async.wait_group %0;" :: "n"(N) : "memory");
}
__device__ __forceinline__ void ldm4(uint32_t* r, uint32_t addr) {
    asm volatile("ldmatrix.sync.aligned.m8n8.x4.shared.b16 {%0,%1,%2,%3}, [%4];"
        : "=r"(r[0]), "=r"(r[1]), "=r"(r[2]), "=r"(r[3]) : "r"(addr));
}
__device__ __forceinline__ void mma16(float* d, const uint32_t* a, uint32_t b0, uint32_t b1) {
    asm volatile("mma.sync.aligned.m16n8k16.row.col.f32.bf16.bf16.f32 "
        "{%0,%1,%2,%3}, {%4,%5,%6,%7}, {%8,%9}, {%0,%1,%2,%3};"
        : "+f"(d[0]), "+f"(d[1]), "+f"(d[2]), "+f"(d[3])
        : "r"(a[0]), "r"(a[1]), "r"(a[2]), "r"(a[3]), "r"(b0), "r"(b1));
}

// ---------------- x transpose + hi/lo bf16 split (unchanged) ---------------
__global__ __launch_bounds__(256) void xpose_kernel(const float* __restrict__ x)
{
    __shared__ float sm[64 * 65];
    const int n0 = blockIdx.x * 64;
    const int c0 = blockIdx.y * 64;
    const int b  = blockIdx.z;
    const int tid = threadIdx.x;

    const float* xb = x + ((size_t)b * CDIM + c0) * NDIM + n0;
    #pragma unroll
    for (int j = 0; j < 4; j++) {
        int idx = tid + 256 * j;
        int cc = idx >> 4, nn4 = idx & 15;
        float4 v = *(const float4*)(xb + (size_t)cc * NDIM + nn4 * 4);
        float* s = sm + cc * 65 + nn4 * 4;
        s[0] = v.x; s[1] = v.y; s[2] = v.z; s[3] = v.w;
    }
    __syncthreads();
    __nv_bfloat16* dh = g_xh + ((size_t)b * NDIM + n0) * CDIM + c0;
    __nv_bfloat16* dl = g_xl + ((size_t)b * NDIM + n0) * CDIM + c0;
    #pragma unroll
    for (int j = 0; j < 8; j++) {
        int idx = tid + 256 * j;
        int nn = idx >> 5, cp = idx & 31;
        float f0 = sm[(2 * cp)     * 65 + nn];
        float f1 = sm[(2 * cp + 1) * 65 + nn];
        float h0 = __bfloat162float(__float2bfloat16(f0));
        float h1 = __bfloat162float(__float2bfloat16(f1));
        *(uint32_t*)(dh + (size_t)nn * CDIM + 2 * cp) = bf2(f0, f1);
        *(uint32_t*)(dl + (size_t)nn * CDIM + 2 * cp) = bf2(f0 - h0, f1 - h1);
    }
}

// ---------------- W hi/lo convert (unchanged) ----------------
__global__ __launch_bounds__(256) void wconv_kernel(
    const float* __restrict__ Wq, const float* __restrict__ Wk,
    const float* __restrict__ Wv, const float* __restrict__ Wp)
{
    const int p = blockIdx.x;
    const float* W = (p == 0) ? Wq : (p == 1) ? Wk : (p == 2) ? Wv : Wp;
    int idx4 = blockIdx.y * 256 + threadIdx.x;
    float4 v = *(const float4*)(W + idx4 * 4);
    float hx = __bfloat162float(__float2bfloat16(v.x));
    float hy = __bfloat162float(__float2bfloat16(v.y));
    float hz = __bfloat162float(__float2bfloat16(v.z));
    float hw = __bfloat162float(__float2bfloat16(v.w));
    uint2 uh = make_uint2(bf2(v.x, v.y), bf2(v.z, v.w));
    uint2 ul = make_uint2(bf2(v.x - hx, v.y - hy), bf2(v.z - hz, v.w - hw));
    *(uint2*)(g_wh + (size_t)p * CDIM * CDIM + idx4 * 4) = uh;
    *(uint2*)(g_wl + (size_t)p * CDIM * CDIM + idx4 * 4) = ul;
}

// ---------------- proj2: bf16 mma projections (unchanged from R12) ---------
__global__ __launch_bounds__(256, 1) void proj2_kernel(
    const float* __restrict__ bq, const float* __restrict__ bk,
    const float* __restrict__ bv, const float* __restrict__ bp,
    float* __restrict__ out)
{
    extern __shared__ char smc[];
    const uint32_t sm0 = smem_u32(smc);
    const int n0 = blockIdx.x * 128;
    const int p  = blockIdx.y;
    const int b  = blockIdx.z;
    const float* bias = (p == 0) ? bq : (p == 1) ? bk : (p == 2) ? bv : bp;
    const bool qk = (p < 2);
    const bool res = (p == 3);

    const int tid = threadIdx.x, lane = tid & 31, w = tid >> 5;
    const int g = lane >> 2, t = lane & 3;
    const int wm  = qk ? (w & 1) : (w >> 1);
    const int wn4 = qk ? (w >> 1) : (w & 1);

    const __nv_bfloat16* xh = g_xh + ((size_t)b * NDIM + n0) * CDIM;
    const __nv_bfloat16* xl = g_xl + ((size_t)b * NDIM + n0) * CDIM;
    const __nv_bfloat16* wh = g_wh + (size_t)p * CDIM * CDIM;
    const __nv_bfloat16* wl = g_wl + (size_t)p * CDIM * CDIM;

    auto load_chunk = [&](int kc, int buf) {
        const uint32_t base = sm0 + (uint32_t)buf * P2_BUF;
        #pragma unroll
        for (int j = 0; j < 4; j++) {
            int idx = tid + 256 * j, r = idx >> 3, ch = idx & 7;
            uint32_t so = (uint32_t)r * 128u + (uint32_t)((ch ^ (r & 7)) << 4);
            cp16(base + P2_XH + so, xh + (size_t)r * CDIM + kc * 64 + ch * 8);
        }
        #pragma unroll
        for (int j = 0; j < 8; j++) {
            int idx = tid + 256 * j, r = idx >> 3, ch = idx & 7;
            uint32_t so = (uint32_t)r * 128u + (uint32_t)((ch ^ (r & 7)) << 4);
            cp16(base + P2_WH + so, wh + (size_t)r * CDIM + kc * 64 + ch * 8);
        }
        if (res) {
            #pragma unroll
            for (int j = 0; j < 4; j++) {
                int idx = tid + 256 * j, r = idx >> 3, ch = idx & 7;
                uint32_t so = (uint32_t)r * 128u + (uint32_t)((ch ^ (r & 7)) << 4);
                cp16(base + P2_XL + so, xl + (size_t)r * CDIM + kc * 64 + ch * 8);
            }
            #pragma unroll
            for (int j = 0; j < 8; j++) {
                int idx = tid + 256 * j, r = idx >> 3, ch = idx & 7;
                uint32_t so = (uint32_t)r * 128u + (uint32_t)((ch ^ (r & 7)) << 4);
                cp16(base + P2_WL + so, wl + (size_t)r * CDIM + kc * 64 + ch * 8);
            }
        }
    };

    load_chunk(0, 0);
    cp_commit();

    const int rA  = ((lane >> 3) & 1) * 8 + (lane & 7);
    const int cAo = lane >> 4;
    const int rB_ = ((lane >> 4) & 1) * 8 + (lane & 7);
    const int cBo = (lane >> 3) & 1;
    const int xs  = lane & 7;

    float acc[4][8][4];
    #pragma unroll
    for (int mf = 0; mf < 4; mf++)
        #pragma unroll
        for (int nf = 0; nf < 8; nf++)
            #pragma unroll
            for (int k = 0; k < 4; k++) acc[mf][nf][k] = 0.f;

    for (int kc = 0; kc < 4; kc++) {
        const int buf = kc & 1;
        cp_wait<0>();
        __syncthreads();
        if (kc + 1 < 4) { load_chunk(kc + 1, buf ^ 1); cp_commit(); }

        const uint32_t base = sm0 + (uint32_t)buf * P2_BUF;
        const uint32_t offA1 = qk ? P2_XH : P2_WH;
        const uint32_t offB1 = qk ? P2_WH : P2_XH;
        const uint32_t aBase = base + (uint32_t)(64 * wm) * 128u + (uint32_t)rA * 128u;
        const uint32_t bBase = base + (uint32_t)(64 * wn4) * 128u + (uint32_t)rB_ * 128u;

        #pragma unroll
        for (int ks = 0; ks < 4; ks++) {
            const uint32_t ao = (uint32_t)(((2 * ks + cAo) ^ xs) << 4);
            const uint32_t bo = (uint32_t)(((2 * ks + cBo) ^ xs) << 4);
            uint32_t b1[4][4];
            #pragma unroll
            for (int nf2 = 0; nf2 < 4; nf2++)
                ldm4(b1[nf2], bBase + offB1 + (uint32_t)nf2 * 2048u + bo);
            if (!res) {
                #pragma unroll
                for (int mf = 0; mf < 4; mf++) {
                    uint32_t ah[4];
                    ldm4(ah, aBase + offA1 + (uint32_t)mf * 2048u + ao);
                    #pragma unroll
                    for (int nf2 = 0; nf2 < 4; nf2++) {
                        mma16(acc[mf][2 * nf2],     ah, b1[nf2][0], b1[nf2][1]);
                        mma16(acc[mf][2 * nf2 + 1], ah, b1[nf2][2], b1[nf2][3]);
                    }
                }
            } else {
                uint32_t b2[4][4];
                #pragma unroll
                for (int nf2 = 0; nf2 < 4; nf2++)
                    ldm4(b2[nf2], bBase + P2_XL + (uint32_t)nf2 * 2048u + bo);
                #pragma unroll
                for (int mf = 0; mf < 4; mf++) {
                    uint32_t ah[4], al[4];
                    ldm4(ah, aBase + P2_WH + (uint32_t)mf * 2048u + ao);
                    ldm4(al, aBase + P2_WL + (uint32_t)mf * 2048u + ao);
                    #pragma unroll
                    for (int nf2 = 0; nf2 < 4; nf2++) {
                        mma16(acc[mf][2 * nf2],     ah, b1[nf2][0], b1[nf2][1]);
                        mma16(acc[mf][2 * nf2 + 1], ah, b1[nf2][2], b1[nf2][3]);
                        mma16(acc[mf][2 * nf2],     ah, b2[nf2][0], b2[nf2][1]);
                        mma16(acc[mf][2 * nf2 + 1], ah, b2[nf2][2], b2[nf2][3]);
                        mma16(acc[mf][2 * nf2],     al, b1[nf2][0], b1[nf2][1]);
                        mma16(acc[mf][2 * nf2 + 1], al, b1[nf2][2], b1[nf2][3]);
                    }
                }
            }
        }
        __syncthreads();
    }

    if (qk) {
        __nv_bfloat16* dst = ((p == 0) ? g_q : g_k) + (size_t)b * NDIM * CDIM;
        #pragma unroll
        for (int mf = 0; mf < 4; mf++) {
            int n = n0 + 64 * wm + 16 * mf + g;
            #pragma unroll
            for (int nf = 0; nf < 8; nf++) {
                int o = 64 * wn4 + 8 * nf + 2 * t;
                float2 bs = *(const float2*)(bias + o);
                *(uint32_t*)(dst + (size_t)n * CDIM + o) =
                    bf2(acc[mf][nf][0] + bs.x, acc[mf][nf][1] + bs.y);
                *(uint32_t*)(dst + (size_t)(n + 8) * CDIM + o) =
                    bf2(acc[mf][nf][2] + bs.x, acc[mf][nf][3] + bs.y);
            }
        }
    } else if (p == 2) {
        __nv_bfloat16* dst = g_v + (size_t)b * CDIM * NDIM;
        #pragma unroll
        for (int mf = 0; mf < 4; mf++) {
            int o = 64 * wm + 16 * mf + g;
            float b0 = bias[o], b8 = bias[o + 8];
            #pragma unroll
            for (int nf = 0; nf < 8; nf++) {
                int n = n0 + 64 * wn4 + 8 * nf + 2 * t;
                *(uint32_t*)(dst + (size_t)o * NDIM + n) =
                    bf2(acc[mf][nf][0] + b0, acc[mf][nf][1] + b0);
                *(uint32_t*)(dst + (size_t)(o + 8) * NDIM + n) =
                    bf2(acc[mf][nf][2] + b8, acc[mf][nf][3] + b8);
            }
        }
    } else {
        float* dst = out + (size_t)b * CDIM * NDIM;
        #pragma unroll
        for (int mf = 0; mf < 4; mf++) {
            int o = 64 * wm + 16 * mf + g;
            float b0 = bias[o], b8 = bias[o + 8];
            #pragma unroll
            for (int nf = 0; nf < 8; nf++) {
                int n = n0 + 64 * wn4 + 8 * nf + 2 * t;
                *(float2*)(dst + (size_t)o * NDIM + n) =
                    make_float2(acc[mf][nf][0] + b0, acc[mf][nf][1] + b0);
                *(float2*)(dst + (size_t)(o + 8) * NDIM + n) =
                    make_float2(acc[mf][nf][2] + b8, acc[mf][nf][3] + b8);
            }
        }
    }
}

// ---------------- K/V tile loader (128 threads, TK=32) ---------------------
// V rows are 64B (4 chunks): swizzle chunk ^= (row>>1)&3 (conflict-free mod 128B)
__device__ __forceinline__ void load_kv(uint32_t sm0, const __nv_bfloat16* kb,
                                        const __nv_bfloat16* vb, int i, int buf, int tid)
{
    const int m0 = i * TK;
    const uint32_t sk = sm0 + SK_OFF + (uint32_t)buf * 16384u;
    const uint32_t sv = sm0 + SV_OFF + (uint32_t)buf * 16384u;
    #pragma unroll
    for (int j = 0; j < 8; j++) {          // K: 32 keys x 256 c (512B rows)
        int idx = tid + 128 * j, r = idx >> 5, ch = idx & 31;
        cp16(sk + (uint32_t)r * 512u + (uint32_t)((ch ^ (r & 7)) << 4),
             kb + (size_t)(m0 + r) * CDIM + ch * 8);
    }
    #pragma unroll
    for (int j = 0; j < 8; j++) {          // V^T: 256 c x 32 keys (64B rows)
        int idx = tid + 128 * j, r = idx >> 2, ch = idx & 3;
        cp16(sv + (uint32_t)r * 64u + (uint32_t)((ch ^ ((r >> 1) & 3)) << 4),
             vb + (size_t)r * NDIM + m0 + ch * 8);
    }
}

// ---------------- bf16 mma flash attention: QR=64, TK=32, 2 CTAs/SM --------
// grid (64, 8), 128 thr, 4 warps. Warp w owns q-rows [16w, 16w+16).
// R10 structure: S warp tile 16x32, register P, PV warp tile 16x256.
__global__ __launch_bounds__(128, 2) void attn_kernel(float* __restrict__ out)
{
    extern __shared__ char smc[];
    const uint32_t sm0 = smem_u32(smc);
    const int tid = threadIdx.x, lane = tid & 31;
    const int w = tid >> 5;
    const int g = lane >> 2, t = lane & 3;
    const int b = blockIdx.y, n0 = blockIdx.x * QR;

    const __nv_bfloat16* qb = g_q + ((size_t)b * NDIM + n0) * CDIM;
    const __nv_bfloat16* kb = g_k + (size_t)b * NDIM * CDIM;
    const __nv_bfloat16* vb = g_v + (size_t)b * CDIM * NDIM;

    // prologue: Q (64x256) + tile0 in one cp.async group
    #pragma unroll
    for (int j = 0; j < 16; j++) {
        int idx = tid + 128 * j, r = idx >> 5, ch = idx & 31;
        cp16(sm0 + SQ_OFF + (uint32_t)r * 512u + (uint32_t)((ch ^ (r & 7)) << 4),
             qb + (size_t)r * CDIM + ch * 8);
    }
    load_kv(sm0, kb, vb, 0, 0, tid);
    cp_commit();

    // ldmatrix lane geometry
    const int rA  = ((lane >> 3) & 1) * 8 + (lane & 7);   // A row-in-16
    const int cAo = lane >> 4;
    const int rB_ = ((lane >> 4) & 1) * 8 + (lane & 7);   // B row-in-16
    const int cBo = (lane >> 3) & 1;
    const int xs  = lane & 7;                             // swizzle XOR (512B rows)
    const int xsv = (lane & 7) >> 1;                      // V swizzle XOR (64B rows)
    const uint32_t qA = sm0 + SQ_OFF + (uint32_t)(16 * w + rA) * 512u;

    float hacc[32][4];
    #pragma unroll
    for (int nf = 0; nf < 32; nf++)
        #pragma unroll
        for (int k = 0; k < 4; k++) hacc[nf][k] = 0.f;
    float lsum0 = 0.f, lsum1 = 0.f;
    const float EC = 0.0901684400555602f;    // log2(e)/16

    for (int i = 0; i < NT; i++) {
        const int buf = i & 1;
        cp_wait<0>();
        __syncthreads();
        if (i + 1 < NT) { load_kv(sm0, kb, vb, i + 1, buf ^ 1, tid); cp_commit(); }

        // ---- S = Q K^T (warp tile 16 rows x 32 keys) ----
        float sacc[4][4];
        #pragma unroll
        for (int f = 0; f < 4; f++)
            #pragma unroll
            for (int k = 0; k < 4; k++) sacc[f][k] = 0.f;
        const uint32_t kB = sm0 + SK_OFF + (uint32_t)buf * 16384u
                          + (uint32_t)rB_ * 512u;
        #pragma unroll
        for (int ks = 0; ks < 16; ks++) {
            uint32_t aq[4];
            ldm4(aq, qA + (uint32_t)(((2 * ks + cAo) ^ xs) << 4));
            uint32_t ko = (uint32_t)(((2 * ks + cBo) ^ xs) << 4);
            #pragma unroll
            for (int nf2 = 0; nf2 < 2; nf2++) {
                uint32_t bk[4];
                ldm4(bk, kB + (uint32_t)nf2 * 8192u + ko);
                mma16(sacc[2 * nf2],     aq, bk[0], bk[1]);
                mma16(sacc[2 * nf2 + 1], aq, bk[2], bk[3]);
            }
        }

        // ---- softmax (max-free) -> PV A-fragments in registers ----
        uint32_t pf[2][4];
        #pragma unroll
        for (int nf = 0; nf < 4; nf++) {
            float e0 = ex2(sacc[nf][0] * EC);
            float e1 = ex2(sacc[nf][1] * EC);
            float e2 = ex2(sacc[nf][2] * EC);
            float e3 = ex2(sacc[nf][3] * EC);
            lsum0 += e0 + e1;
            lsum1 += e2 + e3;
            pf[nf >> 1][(nf & 1) * 2 + 0] = bf2(e0, e1);
            pf[nf >> 1][(nf & 1) * 2 + 1] = bf2(e2, e3);
        }

        // ---- H += P V (warp tile 16 rows x 256 channels, k = 32 keys) ----
        const uint32_t vB = sm0 + SV_OFF + (uint32_t)buf * 16384u
                          + (uint32_t)rB_ * 64u;
        #pragma unroll
        for (int ks = 0; ks < 2; ks++) {
            uint32_t vo = (uint32_t)(((2 * ks + cBo) ^ xsv) << 4);
            #pragma unroll
            for (int nb = 0; nb < 16; nb++) {
                uint32_t bv[4];
                ldm4(bv, vB + (uint32_t)nb * 1024u + vo);
                mma16(hacc[2 * nb],     pf[ks], bv[0], bv[1]);
                mma16(hacc[2 * nb + 1], pf[ks], bv[2], bv[3]);
            }
        }
    }

    // ---- l reduction (t lanes only; warp owns its rows) ----
    lsum0 += __shfl_xor_sync(0xffffffffu, lsum0, 1);
    lsum0 += __shfl_xor_sync(0xffffffffu, lsum0, 2);
    lsum1 += __shfl_xor_sync(0xffffffffu, lsum1, 1);
    lsum1 += __shfl_xor_sync(0xffffffffu, lsum1, 2);
    const float li0 = 1.f / lsum0;
    const float li1 = 1.f / lsum1;

    // ---- epilogue: out[b][c][n] += h / l ----
    const int r0 = 16 * w + g;
    float* ob = out + (size_t)b * CDIM * NDIM + n0;
    #pragma unroll
    for (int nf = 0; nf < 32; nf++) {
        int c = 8 * nf + 2 * t;
        float* d0 = ob + (size_t)c * NDIM + r0;
        float* d1 = d0 + NDIM;
        d0[0] += hacc[nf][0] * li0;
        d1[0] += hacc[nf][1] * li0;
        d0[8] += hacc[nf][2] * li1;
        d1[8] += hacc[nf][3] * li1;
    }
}

extern "C" void kernel_launch(void* const* d_in, const int* in_sizes, int n_in,
                              void* d_out, int out_size)
{
    const float* x  = (const float*)d_in[0];
    const float* Wq = (const float*)d_in[1];
    const float* bq = (const float*)d_in[2];
    const float* Wk = (const float*)d_in[3];
    const float* bk = (const float*)d_in[4];
    const float* Wv = (const float*)d_in[5];
    const float* bv = (const float*)d_in[6];
    const float* Wp = (const float*)d_in[7];
    const float* bp = (const float*)d_in[8];
    float* out = (float*)d_out;

    cudaFuncSetAttribute(proj2_kernel,
                         cudaFuncAttributeMaxDynamicSharedMemorySize, P2_BYTES);
    cudaFuncSetAttribute(attn_kernel,
                         cudaFuncAttributeMaxDynamicSharedMemorySize, SM_BYTES);

    xpose_kernel<<<dim3(64, 4, 8), 256>>>(x);
    wconv_kernel<<<dim3(4, 64), 256>>>(Wq, Wk, Wv, Wp);
    proj2_kernel<<<dim3(32, 4, 8), 256, P2_BYTES>>>(bq, bk, bv, bp, out);
    attn_kernel<<<dim3(NDIM / QR, BDIM), 128, SM_BYTES>>>(out);
}

// round 15
// speedup vs baseline: 1.0570x; 1.0570x over previous
#include <cuda_runtime.h>
#include <cuda_bf16.h>
#include <math.h>
#include <stdint.h>

#define CDIM 256
#define NDIM 4096
#define BDIM 8
#define QR   128
#define TK   64
#define NT   (NDIM / TK)   // 64

__device__ __nv_bfloat16 g_q[(size_t)BDIM * NDIM * CDIM];   // [b][n][c]
__device__ __nv_bfloat16 g_k[(size_t)BDIM * NDIM * CDIM];   // [b][n][c]
__device__ __nv_bfloat16 g_v[(size_t)BDIM * NDIM * CDIM];   // [b][c][n] (transposed)
__device__ __nv_bfloat16 g_xh[(size_t)BDIM * NDIM * CDIM];  // x^T hi [b][n][c]
__device__ __nv_bfloat16 g_xl[(size_t)BDIM * NDIM * CDIM];  // x^T lo
__device__ __nv_bfloat16 g_wh[4 * CDIM * CDIM];             // W hi [p][o][c]
__device__ __nv_bfloat16 g_wl[4 * CDIM * CDIM];             // W lo

// ---- attn smem byte offsets (tile swizzle: 16B chunk ^= row&7) ----
#define SQ_OFF 0u          // 128 x 256 bf16 = 64KB
#define SK_OFF 65536u      // 2 x (64 x 256 bf16) = 64KB
#define SV_OFF 131072u     // 2 x (256 x 64 bf16) = 64KB
#define SM_BYTES 196608u

// ---- proj2 smem byte offsets (per buffer; 2 buffers) ----
#define P2_XH 0u           // 128n x 64c bf16 (row 128B, 8 chunks)
#define P2_XL 16384u       // only loaded for p=3
#define P2_WH 32768u       // 256o x 64c bf16
#define P2_WL 65536u       // only loaded for p=3
#define P2_BUF 98304u
#define P2_BYTES 196608u

// ---------------- helpers ----------------
__device__ __forceinline__ uint32_t smem_u32(const void* p) {
    uint32_t a;
    asm("{ .reg .u64 t; cvta.to.shared.u64 t, %1; cvt.u32.u64 %0, t; }" : "=r"(a) : "l"(p));
    return a;
}
__device__ __forceinline__ float ex2(float x) {
    float y; asm("ex2.approx.f32 %0, %1;" : "=f"(y) : "f"(x)); return y;
}
__device__ __forceinline__ uint32_t bf2(float lo, float hi) {
    __nv_bfloat162 h = __float22bfloat162_rn(make_float2(lo, hi));
    return *(uint32_t*)&h;
}
__device__ __forceinline__ void cp16(uint32_t saddr, const void* gaddr) {
    asm volatile("cp.async.cg.shared.global [%0], [%1], 16;" :: "r"(saddr), "l"(gaddr));
}
__device__ __forceinline__ void cp_commit() {
    asm volatile("cp.async.commit_group;" ::: "memory");
}
template <int N>
__device__ __forceinline__ void cp_wait() {
    asm volatile("cp.async.wait_group %0;" :: "n"(N) : "memory");
}
__device__ __forceinline__ void ldm4(uint32_t* r, uint32_t addr) {
    asm volatile("ldmatrix.sync.aligned.m8n8.x4.shared.b16 {%0,%1,%2,%3}, [%4];"
        : "=r"(r[0]), "=r"(r[1]), "=r"(r[2]), "=r"(r[3]) : "r"(addr));
}
__device__ __forceinline__ void mma16(float* d, const uint32_t* a, uint32_t b0, uint32_t b1) {
    asm volatile("mma.sync.aligned.m16n8k16.row.col.f32.bf16.bf16.f32 "
        "{%0,%1,%2,%3}, {%4,%5,%6,%7}, {%8,%9}, {%0,%1,%2,%3};"
        : "+f"(d[0]), "+f"(d[1]), "+f"(d[2]), "+f"(d[3])
        : "r"(a[0]), "r"(a[1]), "r"(a[2]), "r"(a[3]), "r"(b0), "r"(b1));
}

// ---------------- x transpose + hi/lo bf16 split (unchanged) ---------------
__global__ __launch_bounds__(256) void xpose_kernel(const float* __restrict__ x)
{
    __shared__ float sm[64 * 65];
    const int n0 = blockIdx.x * 64;
    const int c0 = blockIdx.y * 64;
    const int b  = blockIdx.z;
    const int tid = threadIdx.x;

    const float* xb = x + ((size_t)b * CDIM + c0) * NDIM + n0;
    #pragma unroll
    for (int j = 0; j < 4; j++) {
        int idx = tid + 256 * j;
        int cc = idx >> 4, nn4 = idx & 15;
        float4 v = *(const float4*)(xb + (size_t)cc * NDIM + nn4 * 4);
        float* s = sm + cc * 65 + nn4 * 4;
        s[0] = v.x; s[1] = v.y; s[2] = v.z; s[3] = v.w;
    }
    __syncthreads();
    __nv_bfloat16* dh = g_xh + ((size_t)b * NDIM + n0) * CDIM + c0;
    __nv_bfloat16* dl = g_xl + ((size_t)b * NDIM + n0) * CDIM + c0;
    #pragma unroll
    for (int j = 0; j < 8; j++) {
        int idx = tid + 256 * j;
        int nn = idx >> 5, cp = idx & 31;
        float f0 = sm[(2 * cp)     * 65 + nn];
        float f1 = sm[(2 * cp + 1) * 65 + nn];
        float h0 = __bfloat162float(__float2bfloat16(f0));
        float h1 = __bfloat162float(__float2bfloat16(f1));
        *(uint32_t*)(dh + (size_t)nn * CDIM + 2 * cp) = bf2(f0, f1);
        *(uint32_t*)(dl + (size_t)nn * CDIM + 2 * cp) = bf2(f0 - h0, f1 - h1);
    }
}

// ---------------- W hi/lo convert (unchanged) ----------------
__global__ __launch_bounds__(256) void wconv_kernel(
    const float* __restrict__ Wq, const float* __restrict__ Wk,
    const float* __restrict__ Wv, const float* __restrict__ Wp)
{
    const int p = blockIdx.x;
    const float* W = (p == 0) ? Wq : (p == 1) ? Wk : (p == 2) ? Wv : Wp;
    int idx4 = blockIdx.y * 256 + threadIdx.x;
    float4 v = *(const float4*)(W + idx4 * 4);
    float hx = __bfloat162float(__float2bfloat16(v.x));
    float hy = __bfloat162float(__float2bfloat16(v.y));
    float hz = __bfloat162float(__float2bfloat16(v.z));
    float hw = __bfloat162float(__float2bfloat16(v.w));
    uint2 uh = make_uint2(bf2(v.x, v.y), bf2(v.z, v.w));
    uint2 ul = make_uint2(bf2(v.x - hx, v.y - hy), bf2(v.z - hz, v.w - hw));
    *(uint2*)(g_wh + (size_t)p * CDIM * CDIM + idx4 * 4) = uh;
    *(uint2*)(g_wl + (size_t)p * CDIM * CDIM + idx4 * 4) = ul;
}

// ---------------- proj2: bf16 mma projections (R12; heavy p first) ---------
__global__ __launch_bounds__(256, 1) void proj2_kernel(
    const float* __restrict__ bq, const float* __restrict__ bk,
    const float* __restrict__ bv, const float* __restrict__ bp,
    float* __restrict__ out)
{
    extern __shared__ char smc[];
    const uint32_t sm0 = smem_u32(smc);
    const int n0 = blockIdx.x * 128;
    const int p  = blockIdx.y ^ 3;        // run p=3 (3-chain) CTAs first
    const int b  = blockIdx.z;
    const float* bias = (p == 0) ? bq : (p == 1) ? bk : (p == 2) ? bv : bp;
    const bool qk = (p < 2);
    const bool res = (p == 3);

    const int tid = threadIdx.x, lane = tid & 31, w = tid >> 5;
    const int g = lane >> 2, t = lane & 3;
    const int wm  = qk ? (w & 1) : (w >> 1);
    const int wn4 = qk ? (w >> 1) : (w & 1);

    const __nv_bfloat16* xh = g_xh + ((size_t)b * NDIM + n0) * CDIM;
    const __nv_bfloat16* xl = g_xl + ((size_t)b * NDIM + n0) * CDIM;
    const __nv_bfloat16* wh = g_wh + (size_t)p * CDIM * CDIM;
    const __nv_bfloat16* wl = g_wl + (size_t)p * CDIM * CDIM;

    auto load_chunk = [&](int kc, int buf) {
        const uint32_t base = sm0 + (uint32_t)buf * P2_BUF;
        #pragma unroll
        for (int j = 0; j < 4; j++) {
            int idx = tid + 256 * j, r = idx >> 3, ch = idx & 7;
            uint32_t so = (uint32_t)r * 128u + (uint32_t)((ch ^ (r & 7)) << 4);
            cp16(base + P2_XH + so, xh + (size_t)r * CDIM + kc * 64 + ch * 8);
        }
        #pragma unroll
        for (int j = 0; j < 8; j++) {
            int idx = tid + 256 * j, r = idx >> 3, ch = idx & 7;
            uint32_t so = (uint32_t)r * 128u + (uint32_t)((ch ^ (r & 7)) << 4);
            cp16(base + P2_WH + so, wh + (size_t)r * CDIM + kc * 64 + ch * 8);
        }
        if (res) {
            #pragma unroll
            for (int j = 0; j < 4; j++) {
                int idx = tid + 256 * j, r = idx >> 3, ch = idx & 7;
                uint32_t so = (uint32_t)r * 128u + (uint32_t)((ch ^ (r & 7)) << 4);
                cp16(base + P2_XL + so, xl + (size_t)r * CDIM + kc * 64 + ch * 8);
            }
            #pragma unroll
            for (int j = 0; j < 8; j++) {
                int idx = tid + 256 * j, r = idx >> 3, ch = idx & 7;
                uint32_t so = (uint32_t)r * 128u + (uint32_t)((ch ^ (r & 7)) << 4);
                cp16(base + P2_WL + so, wl + (size_t)r * CDIM + kc * 64 + ch * 8);
            }
        }
    };

    load_chunk(0, 0);
    cp_commit();

    const int rA  = ((lane >> 3) & 1) * 8 + (lane & 7);
    const int cAo = lane >> 4;
    const int rB_ = ((lane >> 4) & 1) * 8 + (lane & 7);
    const int cBo = (lane >> 3) & 1;
    const int xs  = lane & 7;

    float acc[4][8][4];
    #pragma unroll
    for (int mf = 0; mf < 4; mf++)
        #pragma unroll
        for (int nf = 0; nf < 8; nf++)
            #pragma unroll
            for (int k = 0; k < 4; k++) acc[mf][nf][k] = 0.f;

    for (int kc = 0; kc < 4; kc++) {
        const int buf = kc & 1;
        cp_wait<0>();
        __syncthreads();
        if (kc + 1 < 4) { load_chunk(kc + 1, buf ^ 1); cp_commit(); }

        const uint32_t base = sm0 + (uint32_t)buf * P2_BUF;
        const uint32_t offA1 = qk ? P2_XH : P2_WH;
        const uint32_t offB1 = qk ? P2_WH : P2_XH;
        const uint32_t aBase = base + (uint32_t)(64 * wm) * 128u + (uint32_t)rA * 128u;
        const uint32_t bBase = base + (uint32_t)(64 * wn4) * 128u + (uint32_t)rB_ * 128u;

        #pragma unroll
        for (int ks = 0; ks < 4; ks++) {
            const uint32_t ao = (uint32_t)(((2 * ks + cAo) ^ xs) << 4);
            const uint32_t bo = (uint32_t)(((2 * ks + cBo) ^ xs) << 4);
            uint32_t b1[4][4];
            #pragma unroll
            for (int nf2 = 0; nf2 < 4; nf2++)
                ldm4(b1[nf2], bBase + offB1 + (uint32_t)nf2 * 2048u + bo);
            if (!res) {
                #pragma unroll
                for (int mf = 0; mf < 4; mf++) {
                    uint32_t ah[4];
                    ldm4(ah, aBase + offA1 + (uint32_t)mf * 2048u + ao);
                    #pragma unroll
                    for (int nf2 = 0; nf2 < 4; nf2++) {
                        mma16(acc[mf][2 * nf2],     ah, b1[nf2][0], b1[nf2][1]);
                        mma16(acc[mf][2 * nf2 + 1], ah, b1[nf2][2], b1[nf2][3]);
                    }
                }
            } else {
                uint32_t b2[4][4];
                #pragma unroll
                for (int nf2 = 0; nf2 < 4; nf2++)
                    ldm4(b2[nf2], bBase + P2_XL + (uint32_t)nf2 * 2048u + bo);
                #pragma unroll
                for (int mf = 0; mf < 4; mf++) {
                    uint32_t ah[4], al[4];
                    ldm4(ah, aBase + P2_WH + (uint32_t)mf * 2048u + ao);
                    ldm4(al, aBase + P2_WL + (uint32_t)mf * 2048u + ao);
                    #pragma unroll
                    for (int nf2 = 0; nf2 < 4; nf2++) {
                        mma16(acc[mf][2 * nf2],     ah, b1[nf2][0], b1[nf2][1]);
                        mma16(acc[mf][2 * nf2 + 1], ah, b1[nf2][2], b1[nf2][3]);
                        mma16(acc[mf][2 * nf2],     ah, b2[nf2][0], b2[nf2][1]);
                        mma16(acc[mf][2 * nf2 + 1], ah, b2[nf2][2], b2[nf2][3]);
                        mma16(acc[mf][2 * nf2],     al, b1[nf2][0], b1[nf2][1]);
                        mma16(acc[mf][2 * nf2 + 1], al, b1[nf2][2], b1[nf2][3]);
                    }
                }
            }
        }
        __syncthreads();
    }

    if (qk) {
        __nv_bfloat16* dst = ((p == 0) ? g_q : g_k) + (size_t)b * NDIM * CDIM;
        #pragma unroll
        for (int mf = 0; mf < 4; mf++) {
            int n = n0 + 64 * wm + 16 * mf + g;
            #pragma unroll
            for (int nf = 0; nf < 8; nf++) {
                int o = 64 * wn4 + 8 * nf + 2 * t;
                float2 bs = *(const float2*)(bias + o);
                *(uint32_t*)(dst + (size_t)n * CDIM + o) =
                    bf2(acc[mf][nf][0] + bs.x, acc[mf][nf][1] + bs.y);
                *(uint32_t*)(dst + (size_t)(n + 8) * CDIM + o) =
                    bf2(acc[mf][nf][2] + bs.x, acc[mf][nf][3] + bs.y);
            }
        }
    } else if (p == 2) {
        __nv_bfloat16* dst = g_v + (size_t)b * CDIM * NDIM;
        #pragma unroll
        for (int mf = 0; mf < 4; mf++) {
            int o = 64 * wm + 16 * mf + g;
            float b0 = bias[o], b8 = bias[o + 8];
            #pragma unroll
            for (int nf = 0; nf < 8; nf++) {
                int n = n0 + 64 * wn4 + 8 * nf + 2 * t;
                *(uint32_t*)(dst + (size_t)o * NDIM + n) =
                    bf2(acc[mf][nf][0] + b0, acc[mf][nf][1] + b0);
                *(uint32_t*)(dst + (size_t)(o + 8) * NDIM + n) =
                    bf2(acc[mf][nf][2] + b8, acc[mf][nf][3] + b8);
            }
        }
    } else {
        float* dst = out + (size_t)b * CDIM * NDIM;
        #pragma unroll
        for (int mf = 0; mf < 4; mf++) {
            int o = 64 * wm + 16 * mf + g;
            float b0 = bias[o], b8 = bias[o + 8];
            #pragma unroll
            for (int nf = 0; nf < 8; nf++) {
                int n = n0 + 64 * wn4 + 8 * nf + 2 * t;
                *(float2*)(dst + (size_t)o * NDIM + n) =
                    make_float2(acc[mf][nf][0] + b0, acc[mf][nf][1] + b0);
                *(float2*)(dst + (size_t)(o + 8) * NDIM + n) =
                    make_float2(acc[mf][nf][2] + b8, acc[mf][nf][3] + b8);
            }
        }
    }
}

// ---------------- K / V tile loaders (separate commit groups) ---------------
__device__ __forceinline__ void load_k(uint32_t sm0, const __nv_bfloat16* kb,
                                       int i, int buf, int tid)
{
    const int m0 = i * TK;
    const uint32_t sk = sm0 + SK_OFF + (uint32_t)buf * 32768u;
    #pragma unroll
    for (int j = 0; j < 8; j++) {          // K: 64 keys x 256 c
        int idx = tid + 256 * j, r = idx >> 5, ch = idx & 31;
        cp16(sk + (uint32_t)r * 512u + (uint32_t)((ch ^ (r & 7)) << 4),
             kb + (size_t)(m0 + r) * CDIM + ch * 8);
    }
}
__device__ __forceinline__ void load_v(uint32_t sm0, const __nv_bfloat16* vb,
                                       int i, int buf, int tid)
{
    const int m0 = i * TK;
    const uint32_t sv = sm0 + SV_OFF + (uint32_t)buf * 32768u;
    #pragma unroll
    for (int j = 0; j < 8; j++) {          // V^T: 256 c x 64 keys
        int idx = tid + 256 * j, r = idx >> 3, ch = idx & 7;
        cp16(sv + (uint32_t)r * 128u + (uint32_t)((ch ^ (r & 7)) << 4),
             vb + (size_t)r * NDIM + m0 + ch * 8);
    }
}

// ---------------- bf16 mma flash attention (R10/R12 + split K/V waits) -----
// grid (32, 8), 256 thr, 8 warps. Warp w owns q-rows [16w, 16w+16).
// S warp tile 16x64; register-resident P; PV warp tile 16x256.
// K and V in separate cp.async groups: S waits only K; PV waits V.
__global__ __launch_bounds__(256, 1) void attn_kernel(float* __restrict__ out)
{
    extern __shared__ char smc[];
    const uint32_t sm0 = smem_u32(smc);
    const int tid = threadIdx.x, lane = tid & 31;
    const int w = tid >> 5;
    const int g = lane >> 2, t = lane & 3;
    const int b = blockIdx.y, n0 = blockIdx.x * QR;

    const __nv_bfloat16* qb = g_q + ((size_t)b * NDIM + n0) * CDIM;
    const __nv_bfloat16* kb = g_k + (size_t)b * NDIM * CDIM;
    const __nv_bfloat16* vb = g_v + (size_t)b * CDIM * NDIM;

    // prologue: group A0 = Q + K0; group B0 = V0
    #pragma unroll
    for (int j = 0; j < 16; j++) {
        int idx = tid + 256 * j, r = idx >> 5, ch = idx & 31;
        cp16(sm0 + SQ_OFF + (uint32_t)r * 512u + (uint32_t)((ch ^ (r & 7)) << 4),
             qb + (size_t)r * CDIM + ch * 8);
    }
    load_k(sm0, kb, 0, 0, tid);
    cp_commit();
    load_v(sm0, vb, 0, 0, tid);
    cp_commit();

    const int rA  = ((lane >> 3) & 1) * 8 + (lane & 7);
    const int cAo = lane >> 4;
    const int rB_ = ((lane >> 4) & 1) * 8 + (lane & 7);
    const int cBo = (lane >> 3) & 1;
    const int xs  = lane & 7;
    const uint32_t qA = sm0 + SQ_OFF + (uint32_t)(16 * w + rA) * 512u;

    float hacc[32][4];
    #pragma unroll
    for (int nf = 0; nf < 32; nf++)
        #pragma unroll
        for (int k = 0; k < 4; k++) hacc[nf][k] = 0.f;
    float lsum0 = 0.f, lsum1 = 0.f;
    const float EC = 0.0901684400555602f;    // log2(e)/16

    for (int i = 0; i < NT; i++) {
        const int buf = i & 1;
        cp_wait<1>();                         // K(i) (+Q) resident; V(i) may fly
        __syncthreads();                      // all warps done with buf^1
        if (i + 1 < NT) {
            load_k(sm0, kb, i + 1, buf ^ 1, tid); cp_commit();
            load_v(sm0, vb, i + 1, buf ^ 1, tid); cp_commit();
        }

        // ---- S = Q K^T (warp tile 16 rows x 64 keys) ----
        float sacc[8][4];
        #pragma unroll
        for (int f = 0; f < 8; f++)
            #pragma unroll
            for (int k = 0; k < 4; k++) sacc[f][k] = 0.f;
        const uint32_t kB = sm0 + SK_OFF + (uint32_t)buf * 32768u
                          + (uint32_t)rB_ * 512u;
        #pragma unroll
        for (int ks = 0; ks < 16; ks++) {
            uint32_t aq[4];
            ldm4(aq, qA + (uint32_t)(((2 * ks + cAo) ^ xs) << 4));
            uint32_t ko = (uint32_t)(((2 * ks + cBo) ^ xs) << 4);
            #pragma unroll
            for (int nf2 = 0; nf2 < 4; nf2++) {
                uint32_t bk[4];
                ldm4(bk, kB + (uint32_t)nf2 * 8192u + ko);
                mma16(sacc[2 * nf2],     aq, bk[0], bk[1]);
                mma16(sacc[2 * nf2 + 1], aq, bk[2], bk[3]);
            }
        }

        // ---- softmax (max-free) -> PV A-fragments in registers ----
        uint32_t pf[4][4];
        #pragma unroll
        for (int nf = 0; nf < 8; nf++) {
            float e0 = ex2(sacc[nf][0] * EC);
            float e1 = ex2(sacc[nf][1] * EC);
            float e2 = ex2(sacc[nf][2] * EC);
            float e3 = ex2(sacc[nf][3] * EC);
            lsum0 += e0 + e1;
            lsum1 += e2 + e3;
            pf[nf >> 1][(nf & 1) * 2 + 0] = bf2(e0, e1);
            pf[nf >> 1][(nf & 1) * 2 + 1] = bf2(e2, e3);
        }

        // V(i) must be resident now (outstanding: A(i+1), B(i+1) if issued)
        if (i + 1 < NT) cp_wait<2>(); else cp_wait<0>();

        // ---- H += P V (warp tile 16 rows x 256 channels, k = 64 keys) ----
        const uint32_t vB = sm0 + SV_OFF + (uint32_t)buf * 32768u
                          + (uint32_t)rB_ * 128u;
        #pragma unroll
        for (int ks = 0; ks < 4; ks++) {
            uint32_t vo = (uint32_t)(((2 * ks + cBo) ^ xs) << 4);
            #pragma unroll
            for (int nb = 0; nb < 16; nb++) {
                uint32_t bv[4];
                ldm4(bv, vB + (uint32_t)nb * 2048u + vo);
                mma16(hacc[2 * nb],     pf[ks], bv[0], bv[1]);
                mma16(hacc[2 * nb + 1], pf[ks], bv[2], bv[3]);
            }
        }
    }

    // ---- l reduction (t lanes only; warp owns its rows) ----
    lsum0 += __shfl_xor_sync(0xffffffffu, lsum0, 1);
    lsum0 += __shfl_xor_sync(0xffffffffu, lsum0, 2);
    lsum1 += __shfl_xor_sync(0xffffffffu, lsum1, 1);
    lsum1 += __shfl_xor_sync(0xffffffffu, lsum1, 2);
    const float li0 = 1.f / lsum0;
    const float li1 = 1.f / lsum1;

    // ---- epilogue: out[b][c][n] += h / l ----
    const int r0 = 16 * w + g;
    float* ob = out + (size_t)b * CDIM * NDIM + n0;
    #pragma unroll
    for (int nf = 0; nf < 32; nf++) {
        int c = 8 * nf + 2 * t;
        float* d0 = ob + (size_t)c * NDIM + r0;
        float* d1 = d0 + NDIM;
        d0[0] += hacc[nf][0] * li0;
        d1[0] += hacc[nf][1] * li0;
        d0[8] += hacc[nf][2] * li1;
        d1[8] += hacc[nf][3] * li1;
    }
}

extern "C" void kernel_launch(void* const* d_in, const int* in_sizes, int n_in,
                              void* d_out, int out_size)
{
    const float* x  = (const float*)d_in[0];
    const float* Wq = (const float*)d_in[1];
    const float* bq = (const float*)d_in[2];
    const float* Wk = (const float*)d_in[3];
    const float* bk = (const float*)d_in[4];
    const float* Wv = (const float*)d_in[5];
    const float* bv = (const float*)d_in[6];
    const float* Wp = (const float*)d_in[7];
    const float* bp = (const float*)d_in[8];
    float* out = (float*)d_out;

    cudaFuncSetAttribute(proj2_kernel,
                         cudaFuncAttributeMaxDynamicSharedMemorySize, P2_BYTES);
    cudaFuncSetAttribute(attn_kernel,
                         cudaFuncAttributeMaxDynamicSharedMemorySize, SM_BYTES);

    xpose_kernel<<<dim3(64, 4, 8), 256>>>(x);
    wconv_kernel<<<dim3(4, 64), 256>>>(Wq, Wk, Wv, Wp);
    proj2_kernel<<<dim3(32, 4, 8), 256, P2_BYTES>>>(bq, bk, bv, bp, out);
    attn_kernel<<<dim3(NDIM / QR, BDIM), 256, SM_BYTES>>>(out);
}

// round 16
// speedup vs baseline: 1.0657x; 1.0082x over previous
#include <cuda_runtime.h>
#include <cuda_bf16.h>
#include <math.h>
#include <stdint.h>

#define CDIM 256
#define NDIM 4096
#define BDIM 8
#define QR   128
#define TK   64
#define NT   (NDIM / TK)   // 64

__device__ __nv_bfloat16 g_q[(size_t)BDIM * NDIM * CDIM];   // [b][n][c]
__device__ __nv_bfloat16 g_k[(size_t)BDIM * NDIM * CDIM];   // [b][n][c]
__device__ __nv_bfloat16 g_v[(size_t)BDIM * NDIM * CDIM];   // [b][c][n] (transposed)
__device__ __nv_bfloat16 g_xh[(size_t)BDIM * NDIM * CDIM];  // x^T hi [b][n][c]
__device__ __nv_bfloat16 g_xl[(size_t)BDIM * NDIM * CDIM];  // x^T lo
__device__ __nv_bfloat16 g_wh[4 * CDIM * CDIM];             // W hi [p][o][c]
__device__ __nv_bfloat16 g_wl[4 * CDIM * CDIM];             // W lo

// ---- attn smem byte offsets (tile swizzle: 16B chunk ^= row&7) ----
#define SQ_OFF 0u          // 128 x 256 bf16 = 64KB
#define SK_OFF 65536u      // 2 x (64 x 256 bf16) = 64KB
#define SV_OFF 131072u     // 2 x (256 x 64 bf16) = 64KB
#define SM_BYTES 196608u

// ---- proj2 smem byte offsets (per buffer; 2 buffers) ----
#define P2_XH 0u           // 128n x 64c bf16 (row 128B, 8 chunks)
#define P2_XL 16384u       // only loaded for p=3
#define P2_WH 32768u       // 256o x 64c bf16
#define P2_WL 65536u       // only loaded for p=3
#define P2_BUF 98304u
#define P2_BYTES 196608u

// ---------------- helpers ----------------
__device__ __forceinline__ uint32_t smem_u32(const void* p) {
    uint32_t a;
    asm("{ .reg .u64 t; cvta.to.shared.u64 t, %1; cvt.u32.u64 %0, t; }" : "=r"(a) : "l"(p));
    return a;
}
__device__ __forceinline__ float ex2(float x) {
    float y; asm("ex2.approx.f32 %0, %1;" : "=f"(y) : "f"(x)); return y;
}
__device__ __forceinline__ uint32_t bf2(float lo, float hi) {
    __nv_bfloat162 h = __float22bfloat162_rn(make_float2(lo, hi));
    return *(uint32_t*)&h;
}
__device__ __forceinline__ void cp16(uint32_t saddr, const void* gaddr) {
    asm volatile("cp.async.cg.shared.global [%0], [%1], 16;" :: "r"(saddr), "l"(gaddr));
}
__device__ __forceinline__ void cp_commit() {
    asm volatile("cp.async.commit_group;" ::: "memory");
}
template <int N>
__device__ __forceinline__ void cp_wait() {
    asm volatile("cp.async.wait_group %0;" :: "n"(N) : "memory");
}
__device__ __forceinline__ void ldm4(uint32_t* r, uint32_t addr) {
    asm volatile("ldmatrix.sync.aligned.m8n8.x4.shared.b16 {%0,%1,%2,%3}, [%4];"
        : "=r"(r[0]), "=r"(r[1]), "=r"(r[2]), "=r"(r[3]) : "r"(addr));
}
__device__ __forceinline__ void mma16(float* d, const uint32_t* a, uint32_t b0, uint32_t b1) {
    asm volatile("mma.sync.aligned.m16n8k16.row.col.f32.bf16.bf16.f32 "
        "{%0,%1,%2,%3}, {%4,%5,%6,%7}, {%8,%9}, {%0,%1,%2,%3};"
        : "+f"(d[0]), "+f"(d[1]), "+f"(d[2]), "+f"(d[3])
        : "r"(a[0]), "r"(a[1]), "r"(a[2]), "r"(a[3]), "r"(b0), "r"(b1));
}

// ---------------- x transpose + hi/lo bf16 split (unchanged) ---------------
__global__ __launch_bounds__(256) void xpose_kernel(const float* __restrict__ x)
{
    __shared__ float sm[64 * 65];
    const int n0 = blockIdx.x * 64;
    const int c0 = blockIdx.y * 64;
    const int b  = blockIdx.z;
    const int tid = threadIdx.x;

    const float* xb = x + ((size_t)b * CDIM + c0) * NDIM + n0;
    #pragma unroll
    for (int j = 0; j < 4; j++) {
        int idx = tid + 256 * j;
        int cc = idx >> 4, nn4 = idx & 15;
        float4 v = *(const float4*)(xb + (size_t)cc * NDIM + nn4 * 4);
        float* s = sm + cc * 65 + nn4 * 4;
        s[0] = v.x; s[1] = v.y; s[2] = v.z; s[3] = v.w;
    }
    __syncthreads();
    __nv_bfloat16* dh = g_xh + ((size_t)b * NDIM + n0) * CDIM + c0;
    __nv_bfloat16* dl = g_xl + ((size_t)b * NDIM + n0) * CDIM + c0;
    #pragma unroll
    for (int j = 0; j < 8; j++) {
        int idx = tid + 256 * j;
        int nn = idx >> 5, cp = idx & 31;
        float f0 = sm[(2 * cp)     * 65 + nn];
        float f1 = sm[(2 * cp + 1) * 65 + nn];
        float h0 = __bfloat162float(__float2bfloat16(f0));
        float h1 = __bfloat162float(__float2bfloat16(f1));
        *(uint32_t*)(dh + (size_t)nn * CDIM + 2 * cp) = bf2(f0, f1);
        *(uint32_t*)(dl + (size_t)nn * CDIM + 2 * cp) = bf2(f0 - h0, f1 - h1);
    }
}

// ---------------- W hi/lo convert (unchanged) ----------------
__global__ __launch_bounds__(256) void wconv_kernel(
    const float* __restrict__ Wq, const float* __restrict__ Wk,
    const float* __restrict__ Wv, const float* __restrict__ Wp)
{
    const int p = blockIdx.x;
    const float* W = (p == 0) ? Wq : (p == 1) ? Wk : (p == 2) ? Wv : Wp;
    int idx4 = blockIdx.y * 256 + threadIdx.x;
    float4 v = *(const float4*)(W + idx4 * 4);
    float hx = __bfloat162float(__float2bfloat16(v.x));
    float hy = __bfloat162float(__float2bfloat16(v.y));
    float hz = __bfloat162float(__float2bfloat16(v.z));
    float hw = __bfloat162float(__float2bfloat16(v.w));
    uint2 uh = make_uint2(bf2(v.x, v.y), bf2(v.z, v.w));
    uint2 ul = make_uint2(bf2(v.x - hx, v.y - hy), bf2(v.z - hz, v.w - hw));
    *(uint2*)(g_wh + (size_t)p * CDIM * CDIM + idx4 * 4) = uh;
    *(uint2*)(g_wl + (size_t)p * CDIM * CDIM + idx4 * 4) = ul;
}

// ---------------- proj2: bf16 mma projections, 512 thr / 16 warps ----------
// grid (32 n-tiles, 4 p, 8 b). CTA: 128n x 256o, K chunks of 64.
// qk: warp = (w&1) n-half x (w>>1) o-eighth; A=X (4 mf), B=W (2 ldm4).
// v/res: warp = (w>>1) o-eighth x (w&1) n-half; A=W (2 mf), B=X (4 ldm4).
// acc = 16 frags = 64 regs/thread. Arithmetic order identical to R12.
__global__ __launch_bounds__(512, 1) void proj2_kernel(
    const float* __restrict__ bq, const float* __restrict__ bk,
    const float* __restrict__ bv, const float* __restrict__ bp,
    float* __restrict__ out)
{
    extern __shared__ char smc[];
    const uint32_t sm0 = smem_u32(smc);
    const int n0 = blockIdx.x * 128;
    const int p  = blockIdx.y;
    const int b  = blockIdx.z;
    const float* bias = (p == 0) ? bq : (p == 1) ? bk : (p == 2) ? bv : bp;
    const bool qk = (p < 2);
    const bool res = (p == 3);

    const int tid = threadIdx.x, lane = tid & 31, w = tid >> 5;
    const int g = lane >> 2, t = lane & 3;
    const int wh2 = w & 1;     // n-half (64 rows)
    const int wo8 = w >> 1;    // o-eighth (32 rows)

    const __nv_bfloat16* xh = g_xh + ((size_t)b * NDIM + n0) * CDIM;
    const __nv_bfloat16* xl = g_xl + ((size_t)b * NDIM + n0) * CDIM;
    const __nv_bfloat16* wph = g_wh + (size_t)p * CDIM * CDIM;
    const __nv_bfloat16* wpl = g_wl + (size_t)p * CDIM * CDIM;

    auto load_chunk = [&](int kc, int buf) {
        const uint32_t base = sm0 + (uint32_t)buf * P2_BUF;
        #pragma unroll
        for (int j = 0; j < 2; j++) {      // XH: 128 rows x 8 ch
            int idx = tid + 512 * j, r = idx >> 3, ch = idx & 7;
            uint32_t so = (uint32_t)r * 128u + (uint32_t)((ch ^ (r & 7)) << 4);
            cp16(base + P2_XH + so, xh + (size_t)r * CDIM + kc * 64 + ch * 8);
        }
        #pragma unroll
        for (int j = 0; j < 4; j++) {      // WH: 256 rows x 8 ch
            int idx = tid + 512 * j, r = idx >> 3, ch = idx & 7;
            uint32_t so = (uint32_t)r * 128u + (uint32_t)((ch ^ (r & 7)) << 4);
            cp16(base + P2_WH + so, wph + (size_t)r * CDIM + kc * 64 + ch * 8);
        }
        if (res) {
            #pragma unroll
            for (int j = 0; j < 2; j++) {  // XL
                int idx = tid + 512 * j, r = idx >> 3, ch = idx & 7;
                uint32_t so = (uint32_t)r * 128u + (uint32_t)((ch ^ (r & 7)) << 4);
                cp16(base + P2_XL + so, xl + (size_t)r * CDIM + kc * 64 + ch * 8);
            }
            #pragma unroll
            for (int j = 0; j < 4; j++) {  // WL
                int idx = tid + 512 * j, r = idx >> 3, ch = idx & 7;
                uint32_t so = (uint32_t)r * 128u + (uint32_t)((ch ^ (r & 7)) << 4);
                cp16(base + P2_WL + so, wpl + (size_t)r * CDIM + kc * 64 + ch * 8);
            }
        }
    };

    load_chunk(0, 0);
    cp_commit();

    const int rA  = ((lane >> 3) & 1) * 8 + (lane & 7);
    const int cAo = lane >> 4;
    const int rB_ = ((lane >> 4) & 1) * 8 + (lane & 7);
    const int cBo = (lane >> 3) & 1;
    const int xs  = lane & 7;

    float acc[16][4];
    #pragma unroll
    for (int f = 0; f < 16; f++)
        #pragma unroll
        for (int k = 0; k < 4; k++) acc[f][k] = 0.f;

    // A/B row bases (bytes within buffer region)
    const uint32_t aRow = qk ? (uint32_t)(64 * wh2 + rA) : (uint32_t)(32 * wo8 + rA);
    const uint32_t bRow = qk ? (uint32_t)(32 * wo8 + rB_) : (uint32_t)(64 * wh2 + rB_);
    const uint32_t offA = qk ? P2_XH : P2_WH;
    const uint32_t offB = qk ? P2_WH : P2_XH;

    for (int kc = 0; kc < 4; kc++) {
        const int buf = kc & 1;
        cp_wait<0>();
        __syncthreads();
        if (kc + 1 < 4) { load_chunk(kc + 1, buf ^ 1); cp_commit(); }

        const uint32_t base = sm0 + (uint32_t)buf * P2_BUF;
        const uint32_t aBase = base + offA + aRow * 128u;
        const uint32_t bBase = base + offB + bRow * 128u;

        #pragma unroll
        for (int ks = 0; ks < 4; ks++) {
            const uint32_t ao = (uint32_t)(((2 * ks + cAo) ^ xs) << 4);
            const uint32_t bo = (uint32_t)(((2 * ks + cBo) ^ xs) << 4);
            if (qk) {
                // A=X (4 mf), B=W (2 ldm4 -> 4 n8)
                uint32_t b1[2][4];
                #pragma unroll
                for (int nf2 = 0; nf2 < 2; nf2++)
                    ldm4(b1[nf2], bBase + (uint32_t)nf2 * 2048u + bo);
                #pragma unroll
                for (int mf = 0; mf < 4; mf++) {
                    uint32_t ah[4];
                    ldm4(ah, aBase + (uint32_t)mf * 2048u + ao);
                    #pragma unroll
                    for (int nf2 = 0; nf2 < 2; nf2++) {
                        mma16(acc[mf * 4 + 2 * nf2],     ah, b1[nf2][0], b1[nf2][1]);
                        mma16(acc[mf * 4 + 2 * nf2 + 1], ah, b1[nf2][2], b1[nf2][3]);
                    }
                }
            } else if (!res) {
                // v: A=W (2 mf), B=X (4 ldm4 -> 8 n8)
                uint32_t b1[4][4];
                #pragma unroll
                for (int nf2 = 0; nf2 < 4; nf2++)
                    ldm4(b1[nf2], bBase + (uint32_t)nf2 * 2048u + bo);
                #pragma unroll
                for (int mf = 0; mf < 2; mf++) {
                    uint32_t ah[4];
                    ldm4(ah, aBase + (uint32_t)mf * 2048u + ao);
                    #pragma unroll
                    for (int nf2 = 0; nf2 < 4; nf2++) {
                        mma16(acc[mf * 8 + 2 * nf2],     ah, b1[nf2][0], b1[nf2][1]);
                        mma16(acc[mf * 8 + 2 * nf2 + 1], ah, b1[nf2][2], b1[nf2][3]);
                    }
                }
            } else {
                // res: Wh*Xh + Wh*Xl + Wl*Xh
                uint32_t b1[4][4], b2[4][4];
                #pragma unroll
                for (int nf2 = 0; nf2 < 4; nf2++) {
                    ldm4(b1[nf2], bBase + (uint32_t)nf2 * 2048u + bo);
                    ldm4(b2[nf2], base + P2_XL + bRow * 128u + (uint32_t)nf2 * 2048u + bo);
                }
                #pragma unroll
                for (int mf = 0; mf < 2; mf++) {
                    uint32_t ah[4], al[4];
                    ldm4(ah, aBase + (uint32_t)mf * 2048u + ao);
                    ldm4(al, base + P2_WL + aRow * 128u + (uint32_t)mf * 2048u + ao);
                    #pragma unroll
                    for (int nf2 = 0; nf2 < 4; nf2++) {
                        mma16(acc[mf * 8 + 2 * nf2],     ah, b1[nf2][0], b1[nf2][1]);
                        mma16(acc[mf * 8 + 2 * nf2 + 1], ah, b1[nf2][2], b1[nf2][3]);
                        mma16(acc[mf * 8 + 2 * nf2],     ah, b2[nf2][0], b2[nf2][1]);
                        mma16(acc[mf * 8 + 2 * nf2 + 1], ah, b2[nf2][2], b2[nf2][3]);
                        mma16(acc[mf * 8 + 2 * nf2],     al, b1[nf2][0], b1[nf2][1]);
                        mma16(acc[mf * 8 + 2 * nf2 + 1], al, b1[nf2][2], b1[nf2][3]);
                    }
                }
            }
        }
        __syncthreads();
    }

    // ---- epilogue ----
    if (qk) {
        __nv_bfloat16* dst = ((p == 0) ? g_q : g_k) + (size_t)b * NDIM * CDIM;
        #pragma unroll
        for (int mf = 0; mf < 4; mf++) {
            int n = n0 + 64 * wh2 + 16 * mf + g;
            #pragma unroll
            for (int nf = 0; nf < 4; nf++) {
                int o = 32 * wo8 + 8 * nf + 2 * t;
                float2 bs = *(const float2*)(bias + o);
                float* a = acc[mf * 4 + nf];
                *(uint32_t*)(dst + (size_t)n * CDIM + o)       = bf2(a[0] + bs.x, a[1] + bs.y);
                *(uint32_t*)(dst + (size_t)(n + 8) * CDIM + o) = bf2(a[2] + bs.x, a[3] + bs.y);
            }
        }
    } else if (p == 2) {
        __nv_bfloat16* dst = g_v + (size_t)b * CDIM * NDIM;
        #pragma unroll
        for (int mf = 0; mf < 2; mf++) {
            int o = 32 * wo8 + 16 * mf + g;
            float b0 = bias[o], b8 = bias[o + 8];
            #pragma unroll
            for (int nf = 0; nf < 8; nf++) {
                int n = n0 + 64 * wh2 + 8 * nf + 2 * t;
                float* a = acc[mf * 8 + nf];
                *(uint32_t*)(dst + (size_t)o * NDIM + n)       = bf2(a[0] + b0, a[1] + b0);
                *(uint32_t*)(dst + (size_t)(o + 8) * NDIM + n) = bf2(a[2] + b8, a[3] + b8);
            }
        }
    } else {
        float* dst = out + (size_t)b * CDIM * NDIM;
        #pragma unroll
        for (int mf = 0; mf < 2; mf++) {
            int o = 32 * wo8 + 16 * mf + g;
            float b0 = bias[o], b8 = bias[o + 8];
            #pragma unroll
            for (int nf = 0; nf < 8; nf++) {
                int n = n0 + 64 * wh2 + 8 * nf + 2 * t;
                float* a = acc[mf * 8 + nf];
                *(float2*)(dst + (size_t)o * NDIM + n)       = make_float2(a[0] + b0, a[1] + b0);
                *(float2*)(dst + (size_t)(o + 8) * NDIM + n) = make_float2(a[2] + b8, a[3] + b8);
            }
        }
    }
}

// ---------------- K/V tile loader (cp.async, bf16, swizzled) ---------------
__device__ __forceinline__ void load_kv(uint32_t sm0, const __nv_bfloat16* kb,
                                        const __nv_bfloat16* vb, int i, int buf, int tid)
{
    const int m0 = i * TK;
    const uint32_t sk = sm0 + SK_OFF + (uint32_t)buf * 32768u;
    const uint32_t sv = sm0 + SV_OFF + (uint32_t)buf * 32768u;
    #pragma unroll
    for (int j = 0; j < 8; j++) {          // K: 64 keys x 256 c
        int idx = tid + 256 * j, r = idx >> 5, ch = idx & 31;
        cp16(sk + (uint32_t)r * 512u + (uint32_t)((ch ^ (r & 7)) << 4),
             kb + (size_t)(m0 + r) * CDIM + ch * 8);
    }
    #pragma unroll
    for (int j = 0; j < 8; j++) {          // V^T: 256 c x 64 keys
        int idx = tid + 256 * j, r = idx >> 3, ch = idx & 7;
        cp16(sv + (uint32_t)r * 128u + (uint32_t)((ch ^ (r & 7)) << 4),
             vb + (size_t)r * NDIM + m0 + ch * 8);
    }
}

// ---------------- bf16 mma flash attention (exact R12 restore) -------------
__global__ __launch_bounds__(256, 1) void attn_kernel(float* __restrict__ out)
{
    extern __shared__ char smc[];
    const uint32_t sm0 = smem_u32(smc);
    const int tid = threadIdx.x, lane = tid & 31;
    const int w = tid >> 5;
    const int g = lane >> 2, t = lane & 3;
    const int b = blockIdx.y, n0 = blockIdx.x * QR;

    const __nv_bfloat16* qb = g_q + ((size_t)b * NDIM + n0) * CDIM;
    const __nv_bfloat16* kb = g_k + (size_t)b * NDIM * CDIM;
    const __nv_bfloat16* vb = g_v + (size_t)b * CDIM * NDIM;

    #pragma unroll
    for (int j = 0; j < 16; j++) {
        int idx = tid + 256 * j, r = idx >> 5, ch = idx & 31;
        cp16(sm0 + SQ_OFF + (uint32_t)r * 512u + (uint32_t)((ch ^ (r & 7)) << 4),
             qb + (size_t)r * CDIM + ch * 8);
    }
    load_kv(sm0, kb, vb, 0, 0, tid);
    cp_commit();

    const int rA  = ((lane >> 3) & 1) * 8 + (lane & 7);
    const int cAo = lane >> 4;
    const int rB_ = ((lane >> 4) & 1) * 8 + (lane & 7);
    const int cBo = (lane >> 3) & 1;
    const int xs  = lane & 7;
    const uint32_t qA = sm0 + SQ_OFF + (uint32_t)(16 * w + rA) * 512u;

    float hacc[32][4];
    #pragma unroll
    for (int nf = 0; nf < 32; nf++)
        #pragma unroll
        for (int k = 0; k < 4; k++) hacc[nf][k] = 0.f;
    float lsum0 = 0.f, lsum1 = 0.f;
    const float EC = 0.0901684400555602f;    // log2(e)/16

    for (int i = 0; i < NT; i++) {
        const int buf = i & 1;
        cp_wait<0>();
        __syncthreads();
        if (i + 1 < NT) { load_kv(sm0, kb, vb, i + 1, buf ^ 1, tid); cp_commit(); }

        float sacc[8][4];
        #pragma unroll
        for (int f = 0; f < 8; f++)
            #pragma unroll
            for (int k = 0; k < 4; k++) sacc[f][k] = 0.f;
        const uint32_t kB = sm0 + SK_OFF + (uint32_t)buf * 32768u
                          + (uint32_t)rB_ * 512u;
        #pragma unroll
        for (int ks = 0; ks < 16; ks++) {
            uint32_t aq[4];
            ldm4(aq, qA + (uint32_t)(((2 * ks + cAo) ^ xs) << 4));
            uint32_t ko = (uint32_t)(((2 * ks + cBo) ^ xs) << 4);
            #pragma unroll
            for (int nf2 = 0; nf2 < 4; nf2++) {
                uint32_t bk[4];
                ldm4(bk, kB + (uint32_t)nf2 * 8192u + ko);
                mma16(sacc[2 * nf2],     aq, bk[0], bk[1]);
                mma16(sacc[2 * nf2 + 1], aq, bk[2], bk[3]);
            }
        }

        uint32_t pf[4][4];
        #pragma unroll
        for (int nf = 0; nf < 8; nf++) {
            float e0 = ex2(sacc[nf][0] * EC);
            float e1 = ex2(sacc[nf][1] * EC);
            float e2 = ex2(sacc[nf][2] * EC);
            float e3 = ex2(sacc[nf][3] * EC);
            lsum0 += e0 + e1;
            lsum1 += e2 + e3;
            pf[nf >> 1][(nf & 1) * 2 + 0] = bf2(e0, e1);
            pf[nf >> 1][(nf & 1) * 2 + 1] = bf2(e2, e3);
        }

        const uint32_t vB = sm0 + SV_OFF + (uint32_t)buf * 32768u
                          + (uint32_t)rB_ * 128u;
        #pragma unroll
        for (int ks = 0; ks < 4; ks++) {
            uint32_t vo = (uint32_t)(((2 * ks + cBo) ^ xs) << 4);
            #pragma unroll
            for (int nb = 0; nb < 16; nb++) {
                uint32_t bv[4];
                ldm4(bv, vB + (uint32_t)nb * 2048u + vo);
                mma16(hacc[2 * nb],     pf[ks], bv[0], bv[1]);
                mma16(hacc[2 * nb + 1], pf[ks], bv[2], bv[3]);
            }
        }
    }

    lsum0 += __shfl_xor_sync(0xffffffffu, lsum0, 1);
    lsum0 += __shfl_xor_sync(0xffffffffu, lsum0, 2);
    lsum1 += __shfl_xor_sync(0xffffffffu, lsum1, 1);
    lsum1 += __shfl_xor_sync(0xffffffffu, lsum1, 2);
    const float li0 = 1.f / lsum0;
    const float li1 = 1.f / lsum1;

    const int r0 = 16 * w + g;
    float* ob = out + (size_t)b * CDIM * NDIM + n0;
    #pragma unroll
    for (int nf = 0; nf < 32; nf++) {
        int c = 8 * nf + 2 * t;
        float* d0 = ob + (size_t)c * NDIM + r0;
        float* d1 = d0 + NDIM;
        d0[0] += hacc[nf][0] * li0;
        d1[0] += hacc[nf][1] * li0;
        d0[8] += hacc[nf][2] * li1;
        d1[8] += hacc[nf][3] * li1;
    }
}

extern "C" void kernel_launch(void* const* d_in, const int* in_sizes, int n_in,
                              void* d_out, int out_size)
{
    const float* x  = (const float*)d_in[0];
    const float* Wq = (const float*)d_in[1];
    const float* bq = (const float*)d_in[2];
    const float* Wk = (const float*)d_in[3];
    const float* bk = (const float*)d_in[4];
    const float* Wv = (const float*)d_in[5];
    const float* bv = (const float*)d_in[6];
    const float* Wp = (const float*)d_in[7];
    const float* bp = (const float*)d_in[8];
    float* out = (float*)d_out;

    cudaFuncSetAttribute(proj2_kernel,
                         cudaFuncAttributeMaxDynamicSharedMemorySize, P2_BYTES);
    cudaFuncSetAttribute(attn_kernel,
                         cudaFuncAttributeMaxDynamicSharedMemorySize, SM_BYTES);

    xpose_kernel<<<dim3(64, 4, 8), 256>>>(x);
    wconv_kernel<<<dim3(4, 64), 256>>>(Wq, Wk, Wv, Wp);
    proj2_kernel<<<dim3(32, 4, 8), 512, P2_BYTES>>>(bq, bk, bv, bp, out);
    attn_kernel<<<dim3(NDIM / QR, BDIM), 256, SM_BYTES>>>(out);
}